// round 15
// baseline (speedup 1.0000x reference)
#include <cuda_runtime.h>
#include <cuda_fp16.h>
#include <math.h>

#define B_   2
#define S_   2048
#define D_   1024
#define H_   8
#define FFN_ 4096
#define DK_  128
#define VD_  2048
#define DV_  256
#define NT_  (B_*S_)
#define BH_  (B_*H_)

#define KC       32
#define TSTRIDE  80
#define TILE_B   (128*TSTRIDE)
#define STAGE_B  (2*TILE_B)
#define NSTAGE   3
#define SMEM_TC  (NSTAGE*STAGE_B)   // 61440
#define NTHREADS 256

// fused retention kernel smem layout (RSTRIDE = 256B payload + 16 pad)
#define RSTRIDE  272
#define SM_Q     0
#define SM_K     (128*RSTRIDE)          // 34816
#define SM_S     (2*128*RSTRIDE)        // 69632
#define SM_V     (3*128*RSTRIDE)        // 104448
#define SMEM_RET (3*128*RSTRIDE + 256*RSTRIDE)   // 174080

typedef __half f16;

// fp32 scratch
__device__ float d_Y  [BH_*S_*DV_];
__device__ float d_X2 [NT_*D_];
__device__ float d_xpt[S_*64*4];
// fp16 buffers
__device__ f16 d_Xn16[NT_*D_];
__device__ f16 d_Wqkv[(size_t)H_*512*D_];
__device__ f16 d_WGT16[VD_*D_];
__device__ f16 d_WOT16[D_*VD_];
__device__ f16 d_W1T16[(size_t)D_*FFN_];
__device__ f16 d_W2T16[(size_t)D_*FFN_];
__device__ f16 d_Q16[BH_*S_*DK_];
__device__ f16 d_K16[BH_*S_*DK_];
__device__ f16 d_V16[BH_*S_*DV_];
__device__ f16 d_Vt16[BH_*DV_*S_];
__device__ f16 d_G16[NT_*VD_];
__device__ f16 d_h116[(size_t)NT_*FFN_];

__device__ __forceinline__ unsigned smem_u32(const void* p) {
    unsigned a;
    asm("{ .reg .u64 t; cvta.to.shared.u64 t, %1; cvt.u32.u64 %0, t; }"
        : "=r"(a) : "l"(p));
    return a;
}
__device__ __forceinline__ unsigned pack2h(float a, float b) {
    unsigned r;
    asm("cvt.rn.f16x2.f32 %0, %1, %2;" : "=r"(r) : "f"(b), "f"(a));
    return r;   // low 16 = a
}
__device__ __forceinline__ void ldm_x4(unsigned* d, unsigned addr) {
    asm volatile("ldmatrix.sync.aligned.m8n8.x4.shared.b16 {%0,%1,%2,%3}, [%4];"
        : "=r"(d[0]), "=r"(d[1]), "=r"(d[2]), "=r"(d[3]) : "r"(addr));
}
__device__ __forceinline__ void mma16816(float* c, const unsigned* a, const unsigned* b) {
    asm volatile("mma.sync.aligned.m16n8k16.row.col.f32.f16.f16.f32 "
        "{%0,%1,%2,%3}, {%4,%5,%6,%7}, {%8,%9}, {%0,%1,%2,%3};"
        : "+f"(c[0]), "+f"(c[1]), "+f"(c[2]), "+f"(c[3])
        : "r"(a[0]), "r"(a[1]), "r"(a[2]), "r"(a[3]), "r"(b[0]), "r"(b[1]));
}
__device__ __forceinline__ void cpa16(unsigned dst, const void* src) {
    asm volatile("cp.async.cg.shared.global [%0], [%1], 16;" :: "r"(dst), "l"(src));
}
#define CP_COMMIT() asm volatile("cp.async.commit_group;" ::: "memory")
#define CP_WAIT1()  asm volatile("cp.async.wait_group 1;" ::: "memory")
#define CP_WAIT0()  asm volatile("cp.async.wait_group 0;" ::: "memory")

// ================= generic fp16 GEMM (R14 config, unchanged) ===============
// mode 3: bias + exact GELU, fp16 out.  mode 4: fp32 + residual.
// mode 5: fp32 + bias + residual.  mode 8: plain fp16 out.
// mode 10: merged per-head QKV routing (Q/K xpos via res=xpt, V plain).
__global__ __launch_bounds__(NTHREADS, 2)
void tcgemm(const f16* __restrict__ A, const f16* __restrict__ Bm,
            void* __restrict__ Cv, void* __restrict__ Cv2, void* __restrict__ Cv3,
            const float* __restrict__ bias, const float* __restrict__ res,
            int N, int K, long long sA, long long sB, long long sC,
            int aDiv, int bMod, int mode)
{
    int bx = blockIdx.x, by = blockIdx.y, bz = blockIdx.z;

    A  += (long long)(bz / aDiv) * sA;
    Bm += (long long)(bz % bMod) * sB;
    int nch = K >> 5;

    extern __shared__ char smem[];
    unsigned sbase = smem_u32(smem);
    int tid = threadIdx.x, wid = tid >> 5, lane = tid & 31;

    int crow = tid >> 1, cch = (tid & 1) * 2;
    const f16* gA = A  + (long long)(by * 128 + crow) * K + cch * 8;
    const f16* gB = Bm + (long long)(bx * 128 + crow) * K + cch * 8;
    unsigned cdst = (unsigned)crow * TSTRIDE + (unsigned)cch * 16;

    int wm = (wid >> 1) * 32;
    int wn = (wid & 1) * 64;
    float acc[2][8][4];
    #pragma unroll
    for (int i = 0; i < 2; i++)
        #pragma unroll
        for (int j = 0; j < 8; j++)
            #pragma unroll
            for (int p = 0; p < 4; p++) acc[i][j][p] = 0.f;

    unsigned a_off = (unsigned)((lane & 15) * TSTRIDE + ((lane >> 4) << 4));
    unsigned b_off = (unsigned)(((lane & 7) + ((lane >> 4) << 3)) * TSTRIDE
                                + (((lane >> 3) & 1) << 4));

    auto prefetch = [&](int s) {
        unsigned d = sbase + (unsigned)(s % NSTAGE) * STAGE_B + cdst;
        long long ko = (long long)s * KC;
        cpa16(d,                 gA + ko);
        cpa16(d + 16,            gA + ko + 8);
        cpa16(d + TILE_B,        gB + ko);
        cpa16(d + TILE_B + 16,   gB + ko + 8);
    };

    prefetch(0); CP_COMMIT();
    if (nch > 1) prefetch(1);
    CP_COMMIT();

    for (int c = 0; c < nch; c++) {
        CP_WAIT1();
        __syncthreads();
        if (c + 2 < nch) prefetch(c + 2);
        CP_COMMIT();

        unsigned sb = sbase + (unsigned)(c % NSTAGE) * STAGE_B;
        #pragma unroll
        for (int ks = 0; ks < 2; ks++) {
            unsigned kb = (unsigned)ks * 32;
            unsigned ah[2][4], bb[4][4];
            #pragma unroll
            for (int mt = 0; mt < 2; mt++)
                ldm_x4(ah[mt], sb + (unsigned)(wm + mt*16) * TSTRIDE + a_off + kb);
            #pragma unroll
            for (int p = 0; p < 4; p++)
                ldm_x4(bb[p], sb + TILE_B + (unsigned)(wn + p*16) * TSTRIDE + b_off + kb);
            #pragma unroll
            for (int mt = 0; mt < 2; mt++)
                #pragma unroll
                for (int nt = 0; nt < 8; nt++)
                    mma16816(acc[mt][nt], ah[mt], &bb[nt>>1][(nt&1)*2]);
        }
    }

    bool f16out = (mode == 3 || mode == 8);
    float* Cf = (float*)Cv + (long long)bz * (f16out || mode == 10 ? 0 : sC);
    unsigned short* Ch = (unsigned short*)Cv + (long long)bz * (f16out ? sC : 0);

    int rbase = by * 128 + wm + (lane >> 2);
    int cbase = bx * 128 + wn + (lane & 3) * 2;
    #pragma unroll
    for (int mt = 0; mt < 2; mt++) {
        #pragma unroll
        for (int half = 0; half < 2; half++) {
            int grow = rbase + mt*16 + half*8;
            #pragma unroll
            for (int nt = 0; nt < 8; nt++) {
                float v0 = acc[mt][nt][half*2], v1 = acc[mt][nt][half*2+1];
                int gcol = cbase + nt*8;
                if (mode == 10) {
                    if (gcol < 256) {
                        int isK = gcol >> 7;
                        int lc  = gcol & 127;
                        const float* t = res + ((long long)grow * 64 + (lc >> 1)) * 4
                                       + isK * 2;
                        float c_ = t[0], s_ = t[1];
                        float o0 = v0 * c_ - v1 * s_;
                        float o1 = v1 * c_ + v0 * s_;
                        f16* dstb = (f16*)(isK ? Cv2 : Cv);
                        *(unsigned*)(dstb + (long long)bz * S_ * DK_
                                     + (long long)grow * DK_ + lc) = pack2h(o0, o1);
                    } else {
                        int lc = gcol - 256;
                        *(unsigned*)((f16*)Cv3 + (long long)bz * S_ * DV_
                                     + (long long)grow * DV_ + lc) = pack2h(v0, v1);
                    }
                    continue;
                }
                if (mode == 3) {
                    float x0 = v0 + bias[gcol], x1 = v1 + bias[gcol+1];
                    v0 = 0.5f*x0*(1.0f + erff(x0*0.70710678118654752f));
                    v1 = 0.5f*x1*(1.0f + erff(x1*0.70710678118654752f));
                } else if (mode == 4) {
                    v0 += res[(long long)grow * N + gcol];
                    v1 += res[(long long)grow * N + gcol + 1];
                } else if (mode == 5) {
                    v0 += bias[gcol]   + res[(long long)grow * N + gcol];
                    v1 += bias[gcol+1] + res[(long long)grow * N + gcol + 1];
                }
                if (f16out) {
                    *(unsigned*)(Ch + (long long)grow * N + gcol) = pack2h(v0, v1);
                } else {
                    *(float2*)(Cf + (long long)grow * N + gcol) = make_float2(v0, v1);
                }
            }
        }
    }
}

// ================= fused retention: Y = (decay ∘ Q K^T) V ==================
// grid (1, S/128, BH), 512 threads. Q,K: [S,128] fp16; Vt: [256,S] fp16.
// Y out fp32 [S, 256] per bz.
__global__ __launch_bounds__(512, 1)
void ret_fused(const f16* __restrict__ Q, const f16* __restrict__ K,
               const f16* __restrict__ Vt, float* __restrict__ Y)
{
    int by = blockIdx.y, bz = blockIdx.z;
    extern __shared__ char smem[];
    unsigned sb = smem_u32(smem);
    int tid = threadIdx.x, wid = tid >> 5, lane = tid & 31;

    const f16* Qb = Q  + (long long)bz * S_ * DK_;
    const f16* Kb = K  + (long long)bz * S_ * DK_;
    const f16* Vb = Vt + (long long)bz * DV_ * S_;

    const float l32 = -3.4657359027997265f, l512 = -6.2383246250395075f;
    float g = 1.0f - expf(l32 + (l512 - l32) * (float)(bz & (H_-1)) * (1.0f/7.0f));
    float lg2g = log2f(g);

    // load mappings
    int qrow = tid >> 2, qc = (tid & 3);            // Q/K: 128 rows, 64B per thread
    unsigned qdst = (unsigned)qrow * RSTRIDE + (unsigned)qc * 64;
    int vrow = tid >> 1, vc = (tid & 1);            // V: 256 rows, 128B per thread
    unsigned vdst = SM_V + (unsigned)vrow * RSTRIDE + (unsigned)vc * 128;

    auto loadQ = [&]() {
        const f16* s = Qb + (long long)(by*128 + qrow) * DK_ + qc * 32;
        #pragma unroll
        for (int j = 0; j < 4; j++) cpa16(sb + qdst + j*16, s + j*8);
    };
    auto loadK = [&](int kt) {
        const f16* s = Kb + (long long)(kt*128 + qrow) * DK_ + qc * 32;
        #pragma unroll
        for (int j = 0; j < 4; j++) cpa16(sb + SM_K + qdst + j*16, s + j*8);
    };
    auto loadV = [&](int kt) {
        const f16* s = Vb + (long long)vrow * S_ + kt*128 + vc * 64;
        #pragma unroll
        for (int j = 0; j < 8; j++) cpa16(sb + vdst + j*16, s + j*8);
    };

    unsigned a_off = (unsigned)((lane & 15) * RSTRIDE + ((lane >> 4) << 4));
    unsigned b_off = (unsigned)(((lane & 7) + ((lane >> 4) << 3)) * RSTRIDE
                                + (((lane >> 3) & 1) << 4));

    // Y accumulators: warp tile 32x64 in 4x4 warp grid over 128x256
    int wmY = (wid >> 2) * 32;
    int wnY = (wid & 3) * 64;
    float accY[2][8][4];
    #pragma unroll
    for (int i = 0; i < 2; i++)
        #pragma unroll
        for (int j = 0; j < 8; j++)
            #pragma unroll
            for (int p = 0; p < 4; p++) accY[i][j][p] = 0.f;

    // S-phase warp mapping: per pass, warp tile 16x32 in 4x4 grid over 64x128
    int wmS = (wid >> 2) * 16;
    int wnS = (wid & 3) * 32;

    loadQ(); loadK(0); loadV(0);
    CP_COMMIT();

    for (int kt = 0; kt <= by; kt++) {
        CP_WAIT0();
        __syncthreads();

        // ---- phase A: S = Q K^T (+decay), two 64-row passes ----
        #pragma unroll
        for (int p = 0; p < 2; p++) {
            int rw = p*64 + wmS;
            float accS[4][4];
            #pragma unroll
            for (int j = 0; j < 4; j++)
                #pragma unroll
                for (int q = 0; q < 4; q++) accS[j][q] = 0.f;
            #pragma unroll
            for (int ks = 0; ks < 8; ks++) {
                unsigned kb = (unsigned)ks * 32;
                unsigned aq[4], bk0[4], bk1[4];
                ldm_x4(aq,  sb + SM_Q + (unsigned)rw * RSTRIDE + a_off + kb);
                ldm_x4(bk0, sb + SM_K + (unsigned)wnS * RSTRIDE + b_off + kb);
                ldm_x4(bk1, sb + SM_K + (unsigned)(wnS+16) * RSTRIDE + b_off + kb);
                mma16816(accS[0], aq, &bk0[0]);
                mma16816(accS[1], aq, &bk0[2]);
                mma16816(accS[2], aq, &bk1[0]);
                mma16816(accS[3], aq, &bk1[2]);
            }
            // decay + store to SM_S
            int r0 = rw + (lane >> 2);
            #pragma unroll
            for (int half = 0; half < 2; half++) {
                int row = r0 + half*8;
                int grow = by*128 + row;
                #pragma unroll
                for (int nt = 0; nt < 4; nt++) {
                    int col = wnS + nt*8 + (lane & 3)*2;
                    int gcol = kt*128 + col;
                    float v0 = accS[nt][half*2], v1 = accS[nt][half*2+1];
                    int d0 = grow - gcol, d1 = d0 - 1;
                    v0 = (d0 >= 0) ? v0 * exp2f((float)d0 * lg2g) : 0.f;
                    v1 = (d1 >= 0) ? v1 * exp2f((float)d1 * lg2g) : 0.f;
                    *(unsigned*)(smem + SM_S + row*RSTRIDE + col*2) = pack2h(v0, v1);
                }
            }
        }
        __syncthreads();   // S visible to all; K consumed

        // ---- phase B: Y += S V ----
        #pragma unroll
        for (int ks = 0; ks < 8; ks++) {
            unsigned kb = (unsigned)ks * 32;
            unsigned as[2][4], bv[4][4];
            #pragma unroll
            for (int mt = 0; mt < 2; mt++)
                ldm_x4(as[mt], sb + SM_S + (unsigned)(wmY + mt*16) * RSTRIDE + a_off + kb);
            #pragma unroll
            for (int p = 0; p < 4; p++)
                ldm_x4(bv[p], sb + SM_V + (unsigned)(wnY + p*16) * RSTRIDE + b_off + kb);
            #pragma unroll
            for (int mt = 0; mt < 2; mt++)
                #pragma unroll
                for (int nt = 0; nt < 8; nt++)
                    mma16816(accY[mt][nt], as[mt], &bv[nt>>1][(nt&1)*2]);
        }
        __syncthreads();   // V consumed

        if (kt < by) { loadK(kt + 1); loadV(kt + 1); }
        CP_COMMIT();
    }

    // ---- epilogue: Y fp32 to global ----
    float* Yb = Y + (long long)bz * S_ * DV_;
    #pragma unroll
    for (int mt = 0; mt < 2; mt++) {
        #pragma unroll
        for (int half = 0; half < 2; half++) {
            int row = wmY + mt*16 + half*8 + (lane >> 2);
            int grow = by*128 + row;
            #pragma unroll
            for (int nt = 0; nt < 8; nt++) {
                int col = wnY + nt*8 + (lane & 3)*2;
                *(float2*)(Yb + (long long)grow * DV_ + col) =
                    make_float2(accY[mt][nt][half*2], accY[mt][nt][half*2+1]);
            }
        }
    }
}

// ================= pre/post kernels =========================================
template<int NT>
__device__ __forceinline__ float blockSum(float v) {
    __shared__ float sh[NT/32];
    int lane = threadIdx.x & 31, w = threadIdx.x >> 5;
    #pragma unroll
    for (int o = 16; o > 0; o >>= 1) v += __shfl_xor_sync(0xffffffffu, v, o);
    if (lane == 0) sh[w] = v;
    __syncthreads();
    float t = 0.f;
    #pragma unroll
    for (int i = 0; i < NT/32; i++) t += sh[i];
    __syncthreads();
    return t;
}

__global__ void wsplit_t(const float* __restrict__ W, f16* __restrict__ T,
                         int K, int N, long long oStride, int rowOff)
{
    __shared__ float t[32][33];
    long long zo = (long long)blockIdx.z * K * N;
    long long oz = (long long)blockIdx.z * oStride;
    int k0 = blockIdx.x*32, n0 = blockIdx.y*32;
    int tx = threadIdx.x, ty = threadIdx.y;
    #pragma unroll
    for (int j = 0; j < 32; j += 8)
        t[ty+j][tx] = W[zo + (long long)(k0+ty+j)*N + n0+tx];
    __syncthreads();
    #pragma unroll
    for (int j = 0; j < 32; j += 8)
        T[oz + (long long)(rowOff + n0+ty+j)*K + k0+tx] = __float2half(t[tx][ty+j]);
}

__global__ void tsp16(const f16* __restrict__ In, f16* __restrict__ T,
                      int K, int N)
{
    __shared__ f16 t[32][33];
    long long zo = (long long)blockIdx.z * K * N;
    int k0 = blockIdx.x*32, n0 = blockIdx.y*32;
    int tx = threadIdx.x, ty = threadIdx.y;
    #pragma unroll
    for (int j = 0; j < 32; j += 8)
        t[ty+j][tx] = In[zo + (long long)(k0+ty+j)*N + n0+tx];
    __syncthreads();
    #pragma unroll
    for (int j = 0; j < 32; j += 8)
        T[zo + (long long)(n0+ty+j)*K + k0+tx] = t[tx][ty+j];
}

__global__ void layernorm_f16(const float* __restrict__ X,
                              const float* __restrict__ w, const float* __restrict__ b,
                              f16* __restrict__ o)
{
    size_t tok = blockIdx.x;
    const float* x = X + tok * D_;
    int t2 = threadIdx.x * 2;
    float2 p0 = *(const float2*)(x + t2);
    float2 p1 = *(const float2*)(x + t2 + 512);
    float s = p0.x + p0.y + p1.x + p1.y;
    float mean = blockSum<256>(s) * (1.0f / D_);
    float d0 = p0.x-mean, d1 = p0.y-mean, d2 = p1.x-mean, d3 = p1.y-mean;
    float var = blockSum<256>(d0*d0 + d1*d1 + d2*d2 + d3*d3) * (1.0f / D_);
    float inv = rsqrtf(var + 1e-5f);
    float o0 = d0*inv*w[t2]     + b[t2];
    float o1 = d1*inv*w[t2+1]   + b[t2+1];
    float o2 = d2*inv*w[t2+512] + b[t2+512];
    float o3 = d3*inv*w[t2+513] + b[t2+513];
    *(unsigned*)(o + tok*D_ + t2)       = pack2h(o0, o1);
    *(unsigned*)(o + tok*D_ + t2 + 512) = pack2h(o2, o3);
}

__global__ void xpos_table_k(float* __restrict__ tab)
{
    int idx = blockIdx.x * 256 + threadIdx.x;
    if (idx >= S_ * 64) return;
    int i = idx & 63, s = idx >> 6;
    double scl = pow((2.0*i + 51.2) / 179.2, (double)s / 512.0);
    float ang_f = (float)s * (float)pow(10000.0, -(double)i / 64.0);
    double sn = sin((double)ang_f), cs = cos((double)ang_f);
    tab[idx*4+0] = (float)(cs * scl);  tab[idx*4+1] = (float)(sn * scl);
    tab[idx*4+2] = (float)(cs / scl);  tab[idx*4+3] = (float)(sn / scl);
}

__global__ void gnorm_gate_f16(const float* __restrict__ Y, const f16* __restrict__ G,
                               const float* __restrict__ w, const float* __restrict__ bb,
                               f16* __restrict__ o)
{
    int h = blockIdx.x % H_, s = (blockIdx.x / H_) % S_, b = blockIdx.x / (H_*S_);
    int v = threadIdx.x;
    size_t yoff = (((size_t)(b*H_+h))*S_ + s)*DV_ + v;
    float y = Y[yoff];
    float mean = blockSum<256>(y) * (1.0f/DV_);
    float d = y - mean;
    float yn = d * rsqrtf(blockSum<256>(d*d)*(1.0f/DV_) + 1e-5f);
    int col = h*DV_ + v;
    size_t goff = ((size_t)(b*S_+s))*VD_ + col;
    float g = __half2float(G[goff]);
    o[goff] = __float2half((g / (1.0f + expf(-g))) * (yn * w[col] + bb[col]));
}

// ================= host launcher ============================================
extern "C" void kernel_launch(void* const* d_in, const int* in_sizes, int n_in,
                              void* d_out, int out_size)
{
    (void)in_sizes; (void)n_in; (void)out_size;
    const float* X      = (const float*)d_in[0];
    const float* Wq     = (const float*)d_in[1];
    const float* Wk     = (const float*)d_in[2];
    const float* Wv     = (const float*)d_in[3];
    const float* W_G    = (const float*)d_in[4];
    const float* W_O    = (const float*)d_in[5];
    const float* gn_w   = (const float*)d_in[6];
    const float* gn_b   = (const float*)d_in[7];
    const float* ln1_w  = (const float*)d_in[8];
    const float* ln1_b  = (const float*)d_in[9];
    const float* ln2_w  = (const float*)d_in[10];
    const float* ln2_b  = (const float*)d_in[11];
    const float* ffn_w1 = (const float*)d_in[12];
    const float* ffn_b1 = (const float*)d_in[13];
    const float* ffn_w2 = (const float*)d_in[14];
    const float* ffn_b2 = (const float*)d_in[15];
    float* out = (float*)d_out;

    float *Y,*X2,*xpt;
    f16 *Xn16,*Wqkv,*WGT,*WOT,*W1T,*W2T,*Q16,*K16,*V16,*Vt16,*G16,*h116;
    cudaGetSymbolAddress((void**)&Y,   d_Y);    cudaGetSymbolAddress((void**)&X2,  d_X2);
    cudaGetSymbolAddress((void**)&xpt, d_xpt);
    cudaGetSymbolAddress((void**)&Xn16,d_Xn16);
    cudaGetSymbolAddress((void**)&Wqkv,d_Wqkv);
    cudaGetSymbolAddress((void**)&WGT, d_WGT16);
    cudaGetSymbolAddress((void**)&WOT, d_WOT16);
    cudaGetSymbolAddress((void**)&W1T, d_W1T16);
    cudaGetSymbolAddress((void**)&W2T, d_W2T16);
    cudaGetSymbolAddress((void**)&Q16, d_Q16);  cudaGetSymbolAddress((void**)&K16, d_K16);
    cudaGetSymbolAddress((void**)&V16, d_V16);  cudaGetSymbolAddress((void**)&Vt16,d_Vt16);
    cudaGetSymbolAddress((void**)&G16, d_G16);  cudaGetSymbolAddress((void**)&h116,d_h116);

    cudaFuncSetAttribute(tcgemm, cudaFuncAttributeMaxDynamicSharedMemorySize, SMEM_TC);
    cudaFuncSetAttribute(ret_fused, cudaFuncAttributeMaxDynamicSharedMemorySize, SMEM_RET);
    dim3 tb(32, 8);

    long long qkvStride = 512LL * D_;
    wsplit_t<<<dim3(D_/32,  DK_/32,  H_), tb>>>(Wq, Wqkv, D_, DK_, qkvStride, 0);
    wsplit_t<<<dim3(D_/32,  DK_/32,  H_), tb>>>(Wk, Wqkv, D_, DK_, qkvStride, 128);
    wsplit_t<<<dim3(D_/32,  DV_/32,  H_), tb>>>(Wv, Wqkv, D_, DV_, qkvStride, 256);
    wsplit_t<<<dim3(D_/32,  VD_/32,  1),  tb>>>(W_G,    WGT, D_,  VD_, (long long)VD_*D_, 0);
    wsplit_t<<<dim3(VD_/32, D_/32,   1),  tb>>>(W_O,    WOT, VD_, D_,  (long long)D_*VD_, 0);
    wsplit_t<<<dim3(D_/32,  FFN_/32, 1),  tb>>>(ffn_w1, W1T, D_,  FFN_,(long long)FFN_*D_, 0);
    wsplit_t<<<dim3(FFN_/32, D_/32,  1),  tb>>>(ffn_w2, W2T, FFN_, D_, (long long)D_*FFN_, 0);
    xpos_table_k<<<(S_*64+255)/256, 256>>>(xpt);

    layernorm_f16<<<NT_, 256>>>(X, ln1_w, ln1_b, Xn16);

    // merged QKV projection per head (fused xpos on Q/K)
    tcgemm<<<dim3(4,16,BH_), NTHREADS, SMEM_TC>>>(Xn16, Wqkv, Q16, K16, V16,
        nullptr, xpt, 512, D_, (long long)S_*D_, qkvStride, 0, H_, H_, 10);

    // G projection (fp16 out)
    tcgemm<<<dim3(16,32,1), NTHREADS, SMEM_TC>>>(Xn16, WGT, G16, nullptr, nullptr,
        nullptr, nullptr, VD_, D_, 0, 0, 0, 1, 1, 8);

    // V transpose fp16
    tsp16<<<dim3(S_/32, DV_/32, BH_), tb>>>(V16, Vt16, S_, DV_);

    // fused retention (scores + decay + ·V)
    ret_fused<<<dim3(1, S_/128, BH_), 512, SMEM_RET>>>(Q16, K16, Vt16, Y);

    // groupnorm + silu gate (in place)
    gnorm_gate_f16<<<B_*S_*H_, 256>>>(Y, G16, gn_w, gn_b, G16);

    // output projection + fused residual (X2 = G·W_O + X)
    tcgemm<<<dim3(8,32,1), NTHREADS, SMEM_TC>>>(G16, WOT, X2, nullptr, nullptr,
        nullptr, X, D_, VD_, 0, 0, 0, 1, 1, 4);

    // ln2 + FFN (bias+GELU fused; final bias+residual fused)
    layernorm_f16<<<NT_, 256>>>(X2, ln2_w, ln2_b, Xn16);
    tcgemm<<<dim3(32,32,1), NTHREADS, SMEM_TC>>>(Xn16, W1T, h116, nullptr, nullptr,
        ffn_b1, nullptr, FFN_, D_, 0, 0, 0, 1, 1, 3);
    tcgemm<<<dim3(8,32,1), NTHREADS, SMEM_TC>>>(h116, W2T, out, nullptr, nullptr,
        ffn_b2, X2, D_, FFN_, 0, 0, 0, 1, 1, 5);
}

// round 16
// speedup vs baseline: 1.0787x; 1.0787x over previous
#include <cuda_runtime.h>
#include <cuda_fp16.h>
#include <math.h>

#define B_   2
#define S_   2048
#define D_   1024
#define H_   8
#define FFN_ 4096
#define DK_  128
#define VD_  2048
#define DV_  256
#define NT_  (B_*S_)
#define BH_  (B_*H_)

#define KC       32
#define TSTRIDE  80
#define TILE_B   (128*TSTRIDE)      // 10240
#define STAGE_B  (2*TILE_B)         // 20480: A, B
#define NSTAGE   3
#define SMEM_TC  (NSTAGE*STAGE_B)   // 61440
#define NTHREADS 256

typedef __half f16;

// fp32 scratch
__device__ float d_Y  [BH_*S_*DV_];
__device__ float d_X2 [NT_*D_];
__device__ float d_xpt[S_*64*4];
// fp16 operand buffers
__device__ f16 d_Xn16[NT_*D_];
__device__ f16 d_Wqkv[(size_t)H_*512*D_];   // per head: Q(128) K(128) V(256) rows
__device__ f16 d_WGT16[VD_*D_];
__device__ f16 d_WOT16[D_*VD_];
__device__ f16 d_W1T16[(size_t)D_*FFN_];
__device__ f16 d_W2T16[(size_t)D_*FFN_];
__device__ f16 d_Q16[BH_*S_*DK_];
__device__ f16 d_K16[BH_*S_*DK_];
__device__ f16 d_Vt16[BH_*DV_*S_];
__device__ f16 d_Sc16[(size_t)BH_*S_*S_];
__device__ f16 d_G16[NT_*VD_];
__device__ f16 d_h116[(size_t)NT_*FFN_];

__device__ __forceinline__ unsigned smem_u32(const void* p) {
    unsigned a;
    asm("{ .reg .u64 t; cvta.to.shared.u64 t, %1; cvt.u32.u64 %0, t; }"
        : "=r"(a) : "l"(p));
    return a;
}
__device__ __forceinline__ unsigned pack2h(float a, float b) {
    unsigned r;
    asm("cvt.rn.f16x2.f32 %0, %1, %2;" : "=r"(r) : "f"(b), "f"(a));
    return r;   // low 16 = a
}
__device__ __forceinline__ void ldm_x4(unsigned* d, unsigned addr) {
    asm volatile("ldmatrix.sync.aligned.m8n8.x4.shared.b16 {%0,%1,%2,%3}, [%4];"
        : "=r"(d[0]), "=r"(d[1]), "=r"(d[2]), "=r"(d[3]) : "r"(addr));
}
__device__ __forceinline__ void mma16816(float* c, const unsigned* a, const unsigned* b) {
    asm volatile("mma.sync.aligned.m16n8k16.row.col.f32.f16.f16.f32 "
        "{%0,%1,%2,%3}, {%4,%5,%6,%7}, {%8,%9}, {%0,%1,%2,%3};"
        : "+f"(c[0]), "+f"(c[1]), "+f"(c[2]), "+f"(c[3])
        : "r"(a[0]), "r"(a[1]), "r"(a[2]), "r"(a[3]), "r"(b[0]), "r"(b[1]));
}
__device__ __forceinline__ void cpa16(unsigned dst, const void* src) {
    asm volatile("cp.async.cg.shared.global [%0], [%1], 16;" :: "r"(dst), "l"(src));
}
#define CP_COMMIT() asm volatile("cp.async.commit_group;" ::: "memory")
#define CP_WAIT1()  asm volatile("cp.async.wait_group 1;" ::: "memory")

// ================= fp16 tensor-core GEMM (R14 config) ======================
// C[z] = A[z/aDiv] * B[z%bMod].  A fp16 row-major [M,K]; B fp16 [N,K] (B^T).
// mode 1: scores — causal tile skip + decay, fp16 out.
// mode 2: retV — K limited to (by+1)*128, fp32 out.
// mode 3: bias + exact GELU, fp16 out.
// mode 4: fp32 out + residual add (res[M,N]).
// mode 5: fp32 out + bias[N] + residual.
// mode 8: plain fp16 out.
// mode 10: merged per-head QKV — route by gcol (Q/K xpos via res=xpt,
//          V written TRANSPOSED into Cv3 = Vt16 [DV, S] per head).
__global__ __launch_bounds__(NTHREADS, 2)
void tcgemm(const f16* __restrict__ A, const f16* __restrict__ Bm,
            void* __restrict__ Cv, void* __restrict__ Cv2, void* __restrict__ Cv3,
            const float* __restrict__ bias, const float* __restrict__ res,
            int N, int K, long long sA, long long sB, long long sC,
            int aDiv, int bMod, int mode)
{
    int bx = blockIdx.x, by = blockIdx.y, bz = blockIdx.z;
    if (mode == 1 && bx > by) return;

    A  += (long long)(bz / aDiv) * sA;
    Bm += (long long)(bz % bMod) * sB;

    int Kuse = (mode == 2) ? min(K, (by + 1) * 128) : K;
    int nch  = Kuse >> 5;

    extern __shared__ char smem[];
    unsigned sbase = smem_u32(smem);
    int tid = threadIdx.x, wid = tid >> 5, lane = tid & 31;

    int crow = tid >> 1, cch = (tid & 1) * 2;
    const f16* gA = A  + (long long)(by * 128 + crow) * K + cch * 8;
    const f16* gB = Bm + (long long)(bx * 128 + crow) * K + cch * 8;
    unsigned cdst = (unsigned)crow * TSTRIDE + (unsigned)cch * 16;

    int wm = (wid >> 1) * 32;
    int wn = (wid & 1) * 64;
    float acc[2][8][4];
    #pragma unroll
    for (int i = 0; i < 2; i++)
        #pragma unroll
        for (int j = 0; j < 8; j++)
            #pragma unroll
            for (int p = 0; p < 4; p++) acc[i][j][p] = 0.f;

    unsigned a_off = (unsigned)((lane & 15) * TSTRIDE + ((lane >> 4) << 4));
    unsigned b_off = (unsigned)(((lane & 7) + ((lane >> 4) << 3)) * TSTRIDE
                                + (((lane >> 3) & 1) << 4));

    auto prefetch = [&](int s) {
        unsigned d = sbase + (unsigned)(s % NSTAGE) * STAGE_B + cdst;
        long long ko = (long long)s * KC;
        cpa16(d,                 gA + ko);
        cpa16(d + 16,            gA + ko + 8);
        cpa16(d + TILE_B,        gB + ko);
        cpa16(d + TILE_B + 16,   gB + ko + 8);
    };

    prefetch(0); CP_COMMIT();
    if (nch > 1) prefetch(1);
    CP_COMMIT();

    for (int c = 0; c < nch; c++) {
        CP_WAIT1();
        __syncthreads();
        if (c + 2 < nch) prefetch(c + 2);
        CP_COMMIT();

        unsigned sb = sbase + (unsigned)(c % NSTAGE) * STAGE_B;
        #pragma unroll
        for (int ks = 0; ks < 2; ks++) {
            unsigned kb = (unsigned)ks * 32;
            unsigned ah[2][4], bb[4][4];
            #pragma unroll
            for (int mt = 0; mt < 2; mt++)
                ldm_x4(ah[mt], sb + (unsigned)(wm + mt*16) * TSTRIDE + a_off + kb);
            #pragma unroll
            for (int p = 0; p < 4; p++)
                ldm_x4(bb[p], sb + TILE_B + (unsigned)(wn + p*16) * TSTRIDE + b_off + kb);
            #pragma unroll
            for (int mt = 0; mt < 2; mt++)
                #pragma unroll
                for (int nt = 0; nt < 8; nt++)
                    mma16816(acc[mt][nt], ah[mt], &bb[nt>>1][(nt&1)*2]);
        }
    }

    // ---------------- epilogue ----------------
    float lg2g = 0.f;
    if (mode == 1) {
        const float l32 = -3.4657359027997265f, l512 = -6.2383246250395075f;
        float g = 1.0f - expf(l32 + (l512 - l32) * (float)(bz & (H_-1)) * (1.0f/7.0f));
        lg2g = log2f(g);
    }
    bool f16out = (mode == 1 || mode == 3 || mode == 8);
    float* Cf = (float*)Cv + (long long)bz * (f16out || mode == 10 ? 0 : sC);
    unsigned short* Ch = (unsigned short*)Cv + (long long)bz * (f16out ? sC : 0);

    int rbase = by * 128 + wm + (lane >> 2);
    int cbase = bx * 128 + wn + (lane & 3) * 2;
    #pragma unroll
    for (int mt = 0; mt < 2; mt++) {
        #pragma unroll
        for (int half = 0; half < 2; half++) {
            int grow = rbase + mt*16 + half*8;
            #pragma unroll
            for (int nt = 0; nt < 8; nt++) {
                float v0 = acc[mt][nt][half*2], v1 = acc[mt][nt][half*2+1];
                int gcol = cbase + nt*8;
                if (mode == 10) {
                    // per-head routing: gcol<128 Q, <256 K, else V (transposed)
                    if (gcol < 256) {
                        int isK = gcol >> 7;
                        int lc  = gcol & 127;
                        const float* t = res + ((long long)grow * 64 + (lc >> 1)) * 4
                                       + isK * 2;
                        float c_ = t[0], s_ = t[1];
                        float o0 = v0 * c_ - v1 * s_;
                        float o1 = v1 * c_ + v0 * s_;
                        f16* dstb = (f16*)(isK ? Cv2 : Cv);
                        *(unsigned*)(dstb + (long long)bz * S_ * DK_
                                     + (long long)grow * DK_ + lc) = pack2h(o0, o1);
                    } else {
                        int lc = gcol - 256;
                        f16* vt = (f16*)Cv3 + (long long)bz * DV_ * S_;
                        vt[(long long)lc * S_ + grow]       = __float2half(v0);
                        vt[(long long)(lc + 1) * S_ + grow] = __float2half(v1);
                    }
                    continue;
                }
                if (mode == 1) {
                    int d0 = grow - gcol, d1 = d0 - 1;
                    v0 = (d0 >= 0) ? v0 * exp2f((float)d0 * lg2g) : 0.f;
                    v1 = (d1 >= 0) ? v1 * exp2f((float)d1 * lg2g) : 0.f;
                } else if (mode == 3) {
                    float x0 = v0 + bias[gcol], x1 = v1 + bias[gcol+1];
                    v0 = 0.5f*x0*(1.0f + erff(x0*0.70710678118654752f));
                    v1 = 0.5f*x1*(1.0f + erff(x1*0.70710678118654752f));
                } else if (mode == 4) {
                    v0 += res[(long long)grow * N + gcol];
                    v1 += res[(long long)grow * N + gcol + 1];
                } else if (mode == 5) {
                    v0 += bias[gcol]   + res[(long long)grow * N + gcol];
                    v1 += bias[gcol+1] + res[(long long)grow * N + gcol + 1];
                }
                if (f16out) {
                    *(unsigned*)(Ch + (long long)grow * N + gcol) = pack2h(v0, v1);
                } else {
                    *(float2*)(Cf + (long long)grow * N + gcol) = make_float2(v0, v1);
                }
            }
        }
    }
}

// ================= pre/post kernels =========================================
template<int NT>
__device__ __forceinline__ float blockSum(float v) {
    __shared__ float sh[NT/32];
    int lane = threadIdx.x & 31, w = threadIdx.x >> 5;
    #pragma unroll
    for (int o = 16; o > 0; o >>= 1) v += __shfl_xor_sync(0xffffffffu, v, o);
    if (lane == 0) sh[w] = v;
    __syncthreads();
    float t = 0.f;
    #pragma unroll
    for (int i = 0; i < NT/32; i++) t += sh[i];
    __syncthreads();
    return t;
}

// transpose + fp16 convert: in [K,N] fp32 (batched) -> out rows at
// z*oStride + (rowOff+n)*K + k
__global__ void wsplit_t(const float* __restrict__ W, f16* __restrict__ T,
                         int K, int N, long long oStride, int rowOff)
{
    __shared__ float t[32][33];
    long long zo = (long long)blockIdx.z * K * N;
    long long oz = (long long)blockIdx.z * oStride;
    int k0 = blockIdx.x*32, n0 = blockIdx.y*32;
    int tx = threadIdx.x, ty = threadIdx.y;
    #pragma unroll
    for (int j = 0; j < 32; j += 8)
        t[ty+j][tx] = W[zo + (long long)(k0+ty+j)*N + n0+tx];
    __syncthreads();
    #pragma unroll
    for (int j = 0; j < 32; j += 8)
        T[oz + (long long)(rowOff + n0+ty+j)*K + k0+tx] = __float2half(t[tx][ty+j]);
}

__global__ void layernorm_f16(const float* __restrict__ X,
                              const float* __restrict__ w, const float* __restrict__ b,
                              f16* __restrict__ o)
{
    size_t tok = blockIdx.x;
    const float* x = X + tok * D_;
    int t2 = threadIdx.x * 2;
    float2 p0 = *(const float2*)(x + t2);
    float2 p1 = *(const float2*)(x + t2 + 512);
    float s = p0.x + p0.y + p1.x + p1.y;
    float mean = blockSum<256>(s) * (1.0f / D_);
    float d0 = p0.x-mean, d1 = p0.y-mean, d2 = p1.x-mean, d3 = p1.y-mean;
    float var = blockSum<256>(d0*d0 + d1*d1 + d2*d2 + d3*d3) * (1.0f / D_);
    float inv = rsqrtf(var + 1e-5f);
    float o0 = d0*inv*w[t2]     + b[t2];
    float o1 = d1*inv*w[t2+1]   + b[t2+1];
    float o2 = d2*inv*w[t2+512] + b[t2+512];
    float o3 = d3*inv*w[t2+513] + b[t2+513];
    *(unsigned*)(o + tok*D_ + t2)       = pack2h(o0, o1);
    *(unsigned*)(o + tok*D_ + t2 + 512) = pack2h(o2, o3);
}

__global__ void xpos_table_k(float* __restrict__ tab)
{
    int idx = blockIdx.x * 256 + threadIdx.x;
    if (idx >= S_ * 64) return;
    int i = idx & 63, s = idx >> 6;
    double scl = pow((2.0*i + 51.2) / 179.2, (double)s / 512.0);
    float ang_f = (float)s * (float)pow(10000.0, -(double)i / 64.0);
    double sn = sin((double)ang_f), cs = cos((double)ang_f);
    tab[idx*4+0] = (float)(cs * scl);  tab[idx*4+1] = (float)(sn * scl);
    tab[idx*4+2] = (float)(cs / scl);  tab[idx*4+3] = (float)(sn / scl);
}

__global__ void gnorm_gate_f16(const float* __restrict__ Y, const f16* __restrict__ G,
                               const float* __restrict__ w, const float* __restrict__ bb,
                               f16* __restrict__ o)
{
    int h = blockIdx.x % H_, s = (blockIdx.x / H_) % S_, b = blockIdx.x / (H_*S_);
    int v = threadIdx.x;
    size_t yoff = (((size_t)(b*H_+h))*S_ + s)*DV_ + v;
    float y = Y[yoff];
    float mean = blockSum<256>(y) * (1.0f/DV_);
    float d = y - mean;
    float yn = d * rsqrtf(blockSum<256>(d*d)*(1.0f/DV_) + 1e-5f);
    int col = h*DV_ + v;
    size_t goff = ((size_t)(b*S_+s))*VD_ + col;
    float g = __half2float(G[goff]);
    o[goff] = __float2half((g / (1.0f + expf(-g))) * (yn * w[col] + bb[col]));
}

// ================= host launcher ============================================
extern "C" void kernel_launch(void* const* d_in, const int* in_sizes, int n_in,
                              void* d_out, int out_size)
{
    (void)in_sizes; (void)n_in; (void)out_size;
    const float* X      = (const float*)d_in[0];
    const float* Wq     = (const float*)d_in[1];
    const float* Wk     = (const float*)d_in[2];
    const float* Wv     = (const float*)d_in[3];
    const float* W_G    = (const float*)d_in[4];
    const float* W_O    = (const float*)d_in[5];
    const float* gn_w   = (const float*)d_in[6];
    const float* gn_b   = (const float*)d_in[7];
    const float* ln1_w  = (const float*)d_in[8];
    const float* ln1_b  = (const float*)d_in[9];
    const float* ln2_w  = (const float*)d_in[10];
    const float* ln2_b  = (const float*)d_in[11];
    const float* ffn_w1 = (const float*)d_in[12];
    const float* ffn_b1 = (const float*)d_in[13];
    const float* ffn_w2 = (const float*)d_in[14];
    const float* ffn_b2 = (const float*)d_in[15];
    float* out = (float*)d_out;

    float *Y,*X2,*xpt;
    f16 *Xn16,*Wqkv,*WGT,*WOT,*W1T,*W2T,*Q16,*K16,*Vt16,*Sc16,*G16,*h116;
    cudaGetSymbolAddress((void**)&Y,   d_Y);    cudaGetSymbolAddress((void**)&X2,  d_X2);
    cudaGetSymbolAddress((void**)&xpt, d_xpt);
    cudaGetSymbolAddress((void**)&Xn16,d_Xn16);
    cudaGetSymbolAddress((void**)&Wqkv,d_Wqkv);
    cudaGetSymbolAddress((void**)&WGT, d_WGT16);
    cudaGetSymbolAddress((void**)&WOT, d_WOT16);
    cudaGetSymbolAddress((void**)&W1T, d_W1T16);
    cudaGetSymbolAddress((void**)&W2T, d_W2T16);
    cudaGetSymbolAddress((void**)&Q16, d_Q16);  cudaGetSymbolAddress((void**)&K16, d_K16);
    cudaGetSymbolAddress((void**)&Vt16,d_Vt16);
    cudaGetSymbolAddress((void**)&Sc16,d_Sc16);
    cudaGetSymbolAddress((void**)&G16, d_G16);  cudaGetSymbolAddress((void**)&h116,d_h116);

    cudaFuncSetAttribute(tcgemm, cudaFuncAttributeMaxDynamicSharedMemorySize, SMEM_TC);
    dim3 tb(32, 8);

    long long qkvStride = 512LL * D_;
    wsplit_t<<<dim3(D_/32,  DK_/32,  H_), tb>>>(Wq, Wqkv, D_, DK_, qkvStride, 0);
    wsplit_t<<<dim3(D_/32,  DK_/32,  H_), tb>>>(Wk, Wqkv, D_, DK_, qkvStride, 128);
    wsplit_t<<<dim3(D_/32,  DV_/32,  H_), tb>>>(Wv, Wqkv, D_, DV_, qkvStride, 256);
    wsplit_t<<<dim3(D_/32,  VD_/32,  1),  tb>>>(W_G,    WGT, D_,  VD_, (long long)VD_*D_, 0);
    wsplit_t<<<dim3(VD_/32, D_/32,   1),  tb>>>(W_O,    WOT, VD_, D_,  (long long)D_*VD_, 0);
    wsplit_t<<<dim3(D_/32,  FFN_/32, 1),  tb>>>(ffn_w1, W1T, D_,  FFN_,(long long)FFN_*D_, 0);
    wsplit_t<<<dim3(FFN_/32, D_/32,  1),  tb>>>(ffn_w2, W2T, FFN_, D_, (long long)D_*FFN_, 0);
    xpos_table_k<<<(S_*64+255)/256, 256>>>(xpt);

    // ln1
    layernorm_f16<<<NT_, 256>>>(X, ln1_w, ln1_b, Xn16);

    // merged QKV projection per head (fused xpos on Q/K, V written transposed)
    tcgemm<<<dim3(4,16,BH_), NTHREADS, SMEM_TC>>>(Xn16, Wqkv, Q16, K16, Vt16,
        nullptr, xpt, 512, D_,
        (long long)S_*D_, qkvStride, 0, H_, H_, 10);

    // G projection (fp16 out)
    tcgemm<<<dim3(16,32,1), NTHREADS, SMEM_TC>>>(Xn16, WGT, G16, nullptr, nullptr,
        nullptr, nullptr, VD_, D_, 0, 0, 0, 1, 1, 8);

    // scores = Q K^T (fused causal decay, fp16 out)
    tcgemm<<<dim3(16,16,BH_), NTHREADS, SMEM_TC>>>(Q16, K16, Sc16, nullptr, nullptr,
        nullptr, nullptr, S_, DK_,
        (long long)S_*DK_, (long long)S_*DK_, (long long)S_*S_, 1, BH_, 1);
    // Y = Sc V  (K-limited, fp32 out)
    tcgemm<<<dim3(2,16,BH_), NTHREADS, SMEM_TC>>>(Sc16, Vt16, Y, nullptr, nullptr,
        nullptr, nullptr, DV_, S_,
        (long long)S_*S_, (long long)DV_*S_, (long long)S_*DV_, 1, BH_, 2);

    // groupnorm + silu gate (in place)
    gnorm_gate_f16<<<B_*S_*H_, 256>>>(Y, G16, gn_w, gn_b, G16);

    // output projection + fused residual (X2 = G·W_O + X)
    tcgemm<<<dim3(8,32,1), NTHREADS, SMEM_TC>>>(G16, WOT, X2, nullptr, nullptr,
        nullptr, X, D_, VD_, 0, 0, 0, 1, 1, 4);

    // ln2 + FFN (bias+GELU fused; final bias+residual fused)
    layernorm_f16<<<NT_, 256>>>(X2, ln2_w, ln2_b, Xn16);
    tcgemm<<<dim3(32,32,1), NTHREADS, SMEM_TC>>>(Xn16, W1T, h116, nullptr, nullptr,
        ffn_b1, nullptr, FFN_, D_, 0, 0, 0, 1, 1, 3);
    tcgemm<<<dim3(8,32,1), NTHREADS, SMEM_TC>>>(h116, W2T, out, nullptr, nullptr,
        ffn_b2, X2, D_, FFN_, 0, 0, 0, 1, 1, 5);
}

// round 17
// speedup vs baseline: 1.0886x; 1.0092x over previous
#include <cuda_runtime.h>
#include <cuda_fp16.h>
#include <math.h>

#define B_   2
#define S_   2048
#define D_   1024
#define H_   8
#define FFN_ 4096
#define DK_  128
#define VD_  2048
#define DV_  256
#define NT_  (B_*S_)
#define BH_  (B_*H_)

#define KC       32
#define TSTRIDE  80
#define TILE_B   (128*TSTRIDE)      // 10240
#define STAGE_B  (2*TILE_B)         // 20480: A, B
#define NSTAGE   3
#define SMEM_TC  (NSTAGE*STAGE_B)   // 61440
#define NTHREADS 256

typedef __half f16;

// fp32 scratch
__device__ float d_Y  [BH_*S_*DV_];
__device__ float d_X2 [NT_*D_];
__device__ float d_xpt[S_*64*4];
// fp16 operand buffers
__device__ f16 d_Xn16[NT_*D_];
__device__ f16 d_Wqkv[(size_t)H_*512*D_];   // per head: Q(128) K(128) V(256) rows
__device__ f16 d_WGT16[VD_*D_];
__device__ f16 d_WOT16[D_*VD_];
__device__ f16 d_W1T16[(size_t)D_*FFN_];
__device__ f16 d_W2T16[(size_t)D_*FFN_];
__device__ f16 d_Q16[BH_*S_*DK_];
__device__ f16 d_K16[BH_*S_*DK_];
__device__ f16 d_Vt16[BH_*DV_*S_];
__device__ f16 d_Sc16[(size_t)BH_*S_*S_];
__device__ f16 d_G16[NT_*VD_];
__device__ f16 d_h116[(size_t)NT_*FFN_];

__device__ __forceinline__ unsigned smem_u32(const void* p) {
    unsigned a;
    asm("{ .reg .u64 t; cvta.to.shared.u64 t, %1; cvt.u32.u64 %0, t; }"
        : "=r"(a) : "l"(p));
    return a;
}
__device__ __forceinline__ unsigned pack2h(float a, float b) {
    unsigned r;
    asm("cvt.rn.f16x2.f32 %0, %1, %2;" : "=r"(r) : "f"(b), "f"(a));
    return r;   // low 16 = a
}
__device__ __forceinline__ void ldm_x4(unsigned* d, unsigned addr) {
    asm volatile("ldmatrix.sync.aligned.m8n8.x4.shared.b16 {%0,%1,%2,%3}, [%4];"
        : "=r"(d[0]), "=r"(d[1]), "=r"(d[2]), "=r"(d[3]) : "r"(addr));
}
__device__ __forceinline__ void mma16816(float* c, const unsigned* a, const unsigned* b) {
    asm volatile("mma.sync.aligned.m16n8k16.row.col.f32.f16.f16.f32 "
        "{%0,%1,%2,%3}, {%4,%5,%6,%7}, {%8,%9}, {%0,%1,%2,%3};"
        : "+f"(c[0]), "+f"(c[1]), "+f"(c[2]), "+f"(c[3])
        : "r"(a[0]), "r"(a[1]), "r"(a[2]), "r"(a[3]), "r"(b[0]), "r"(b[1]));
}
__device__ __forceinline__ void cpa16(unsigned dst, const void* src) {
    asm volatile("cp.async.cg.shared.global [%0], [%1], 16;" :: "r"(dst), "l"(src));
}
#define CP_COMMIT() asm volatile("cp.async.commit_group;" ::: "memory")
#define CP_WAIT1()  asm volatile("cp.async.wait_group 1;" ::: "memory")

// ================= fp16 tensor-core GEMM (R16 config, unchanged) ===========
// mode 1: scores — causal tile skip + decay, fp16 out.
// mode 2: retV — K limited to (by+1)*128, fp32 out.
// mode 3: bias + exact GELU, fp16 out.
// mode 4: fp32 out + residual add (res[M,N]).
// mode 5: fp32 out + bias[N] + residual.
// mode 8: plain fp16 out.
// mode 10: merged per-head QKV — Q/K xpos via res=xpt; V written transposed.
__global__ __launch_bounds__(NTHREADS, 2)
void tcgemm(const f16* __restrict__ A, const f16* __restrict__ Bm,
            void* __restrict__ Cv, void* __restrict__ Cv2, void* __restrict__ Cv3,
            const float* __restrict__ bias, const float* __restrict__ res,
            int N, int K, long long sA, long long sB, long long sC,
            int aDiv, int bMod, int mode)
{
    int bx = blockIdx.x, by = blockIdx.y, bz = blockIdx.z;
    if (mode == 1 && bx > by) return;

    A  += (long long)(bz / aDiv) * sA;
    Bm += (long long)(bz % bMod) * sB;

    int Kuse = (mode == 2) ? min(K, (by + 1) * 128) : K;
    int nch  = Kuse >> 5;

    extern __shared__ char smem[];
    unsigned sbase = smem_u32(smem);
    int tid = threadIdx.x, wid = tid >> 5, lane = tid & 31;

    int crow = tid >> 1, cch = (tid & 1) * 2;
    const f16* gA = A  + (long long)(by * 128 + crow) * K + cch * 8;
    const f16* gB = Bm + (long long)(bx * 128 + crow) * K + cch * 8;
    unsigned cdst = (unsigned)crow * TSTRIDE + (unsigned)cch * 16;

    int wm = (wid >> 1) * 32;
    int wn = (wid & 1) * 64;
    float acc[2][8][4];
    #pragma unroll
    for (int i = 0; i < 2; i++)
        #pragma unroll
        for (int j = 0; j < 8; j++)
            #pragma unroll
            for (int p = 0; p < 4; p++) acc[i][j][p] = 0.f;

    unsigned a_off = (unsigned)((lane & 15) * TSTRIDE + ((lane >> 4) << 4));
    unsigned b_off = (unsigned)(((lane & 7) + ((lane >> 4) << 3)) * TSTRIDE
                                + (((lane >> 3) & 1) << 4));

    auto prefetch = [&](int s) {
        unsigned d = sbase + (unsigned)(s % NSTAGE) * STAGE_B + cdst;
        long long ko = (long long)s * KC;
        cpa16(d,                 gA + ko);
        cpa16(d + 16,            gA + ko + 8);
        cpa16(d + TILE_B,        gB + ko);
        cpa16(d + TILE_B + 16,   gB + ko + 8);
    };

    prefetch(0); CP_COMMIT();
    if (nch > 1) prefetch(1);
    CP_COMMIT();

    for (int c = 0; c < nch; c++) {
        CP_WAIT1();
        __syncthreads();
        if (c + 2 < nch) prefetch(c + 2);
        CP_COMMIT();

        unsigned sb = sbase + (unsigned)(c % NSTAGE) * STAGE_B;
        #pragma unroll
        for (int ks = 0; ks < 2; ks++) {
            unsigned kb = (unsigned)ks * 32;
            unsigned ah[2][4], bb[4][4];
            #pragma unroll
            for (int mt = 0; mt < 2; mt++)
                ldm_x4(ah[mt], sb + (unsigned)(wm + mt*16) * TSTRIDE + a_off + kb);
            #pragma unroll
            for (int p = 0; p < 4; p++)
                ldm_x4(bb[p], sb + TILE_B + (unsigned)(wn + p*16) * TSTRIDE + b_off + kb);
            #pragma unroll
            for (int mt = 0; mt < 2; mt++)
                #pragma unroll
                for (int nt = 0; nt < 8; nt++)
                    mma16816(acc[mt][nt], ah[mt], &bb[nt>>1][(nt&1)*2]);
        }
    }

    // ---------------- epilogue ----------------
    float lg2g = 0.f;
    if (mode == 1) {
        const float l32 = -3.4657359027997265f, l512 = -6.2383246250395075f;
        float g = 1.0f - expf(l32 + (l512 - l32) * (float)(bz & (H_-1)) * (1.0f/7.0f));
        lg2g = log2f(g);
    }
    bool f16out = (mode == 1 || mode == 3 || mode == 8);
    float* Cf = (float*)Cv + (long long)bz * (f16out || mode == 10 ? 0 : sC);
    unsigned short* Ch = (unsigned short*)Cv + (long long)bz * (f16out ? sC : 0);

    int rbase = by * 128 + wm + (lane >> 2);
    int cbase = bx * 128 + wn + (lane & 3) * 2;
    #pragma unroll
    for (int mt = 0; mt < 2; mt++) {
        #pragma unroll
        for (int half = 0; half < 2; half++) {
            int grow = rbase + mt*16 + half*8;
            #pragma unroll
            for (int nt = 0; nt < 8; nt++) {
                float v0 = acc[mt][nt][half*2], v1 = acc[mt][nt][half*2+1];
                int gcol = cbase + nt*8;
                if (mode == 10) {
                    if (gcol < 256) {
                        int isK = gcol >> 7;
                        int lc  = gcol & 127;
                        const float* t = res + ((long long)grow * 64 + (lc >> 1)) * 4
                                       + isK * 2;
                        float c_ = t[0], s_ = t[1];
                        float o0 = v0 * c_ - v1 * s_;
                        float o1 = v1 * c_ + v0 * s_;
                        f16* dstb = (f16*)(isK ? Cv2 : Cv);
                        *(unsigned*)(dstb + (long long)bz * S_ * DK_
                                     + (long long)grow * DK_ + lc) = pack2h(o0, o1);
                    } else {
                        int lc = gcol - 256;
                        f16* vt = (f16*)Cv3 + (long long)bz * DV_ * S_;
                        vt[(long long)lc * S_ + grow]       = __float2half(v0);
                        vt[(long long)(lc + 1) * S_ + grow] = __float2half(v1);
                    }
                    continue;
                }
                if (mode == 1) {
                    int d0 = grow - gcol, d1 = d0 - 1;
                    v0 = (d0 >= 0) ? v0 * exp2f((float)d0 * lg2g) : 0.f;
                    v1 = (d1 >= 0) ? v1 * exp2f((float)d1 * lg2g) : 0.f;
                } else if (mode == 3) {
                    float x0 = v0 + bias[gcol], x1 = v1 + bias[gcol+1];
                    v0 = 0.5f*x0*(1.0f + erff(x0*0.70710678118654752f));
                    v1 = 0.5f*x1*(1.0f + erff(x1*0.70710678118654752f));
                } else if (mode == 4) {
                    v0 += res[(long long)grow * N + gcol];
                    v1 += res[(long long)grow * N + gcol + 1];
                } else if (mode == 5) {
                    v0 += bias[gcol]   + res[(long long)grow * N + gcol];
                    v1 += bias[gcol+1] + res[(long long)grow * N + gcol + 1];
                }
                if (f16out) {
                    *(unsigned*)(Ch + (long long)grow * N + gcol) = pack2h(v0, v1);
                } else {
                    *(float2*)(Cf + (long long)grow * N + gcol) = make_float2(v0, v1);
                }
            }
        }
    }
}

// ================= merged weight prep (7 transposes, 1 launch) ==============
struct WJobs {
    const float* src[7];
    f16*         dst[7];
    int K[7], N[7], rOff[7];
    long long oS[7];
    int start[8];
};

__global__ void wsplit_all(WJobs J)
{
    __shared__ float t[32][33];
    int b = blockIdx.x;
    int j = 0;
    #pragma unroll
    for (int i = 0; i < 6; i++) if (b >= J.start[i+1]) j = i + 1;
    int local = b - J.start[j];
    int K = J.K[j], N = J.N[j];
    int kt = K >> 5;
    int tpz = kt * (N >> 5);
    int z = local / tpz, tt = local - z * tpz;
    int k0 = (tt % kt) << 5, n0 = (tt / kt) << 5;

    const float* W = J.src[j] + (long long)z * K * N;
    f16* T = J.dst[j] + (long long)z * J.oS[j];
    int rowOff = J.rOff[j];
    int tx = threadIdx.x, ty = threadIdx.y;
    #pragma unroll
    for (int jj = 0; jj < 32; jj += 8)
        t[ty+jj][tx] = W[(long long)(k0+ty+jj)*N + n0+tx];
    __syncthreads();
    #pragma unroll
    for (int jj = 0; jj < 32; jj += 8)
        T[(long long)(rowOff + n0+ty+jj)*K + k0+tx] = __float2half(t[tx][ty+jj]);
}

// ================= pre/post kernels =========================================
template<int NT>
__device__ __forceinline__ float blockSum(float v) {
    __shared__ float sh[NT/32];
    int lane = threadIdx.x & 31, w = threadIdx.x >> 5;
    #pragma unroll
    for (int o = 16; o > 0; o >>= 1) v += __shfl_xor_sync(0xffffffffu, v, o);
    if (lane == 0) sh[w] = v;
    __syncthreads();
    float t = 0.f;
    #pragma unroll
    for (int i = 0; i < NT/32; i++) t += sh[i];
    __syncthreads();
    return t;
}

__global__ void layernorm_f16(const float* __restrict__ X,
                              const float* __restrict__ w, const float* __restrict__ b,
                              f16* __restrict__ o)
{
    size_t tok = blockIdx.x;
    const float* x = X + tok * D_;
    int t2 = threadIdx.x * 2;
    float2 p0 = *(const float2*)(x + t2);
    float2 p1 = *(const float2*)(x + t2 + 512);
    float s = p0.x + p0.y + p1.x + p1.y;
    float mean = blockSum<256>(s) * (1.0f / D_);
    float d0 = p0.x-mean, d1 = p0.y-mean, d2 = p1.x-mean, d3 = p1.y-mean;
    float var = blockSum<256>(d0*d0 + d1*d1 + d2*d2 + d3*d3) * (1.0f / D_);
    float inv = rsqrtf(var + 1e-5f);
    float o0 = d0*inv*w[t2]     + b[t2];
    float o1 = d1*inv*w[t2+1]   + b[t2+1];
    float o2 = d2*inv*w[t2+512] + b[t2+512];
    float o3 = d3*inv*w[t2+513] + b[t2+513];
    *(unsigned*)(o + tok*D_ + t2)       = pack2h(o0, o1);
    *(unsigned*)(o + tok*D_ + t2 + 512) = pack2h(o2, o3);
}

__global__ void xpos_table_k(float* __restrict__ tab)
{
    int idx = blockIdx.x * 256 + threadIdx.x;
    if (idx >= S_ * 64) return;
    int i = idx & 63, s = idx >> 6;
    double scl = pow((2.0*i + 51.2) / 179.2, (double)s / 512.0);
    float ang_f = (float)s * (float)pow(10000.0, -(double)i / 64.0);
    double sn = sin((double)ang_f), cs = cos((double)ang_f);
    tab[idx*4+0] = (float)(cs * scl);  tab[idx*4+1] = (float)(sn * scl);
    tab[idx*4+2] = (float)(cs / scl);  tab[idx*4+3] = (float)(sn / scl);
}

__global__ void gnorm_gate_f16(const float* __restrict__ Y, const f16* __restrict__ G,
                               const float* __restrict__ w, const float* __restrict__ bb,
                               f16* __restrict__ o)
{
    int h = blockIdx.x % H_, s = (blockIdx.x / H_) % S_, b = blockIdx.x / (H_*S_);
    int v = threadIdx.x;
    size_t yoff = (((size_t)(b*H_+h))*S_ + s)*DV_ + v;
    float y = Y[yoff];
    float mean = blockSum<256>(y) * (1.0f/DV_);
    float d = y - mean;
    float yn = d * rsqrtf(blockSum<256>(d*d)*(1.0f/DV_) + 1e-5f);
    int col = h*DV_ + v;
    size_t goff = ((size_t)(b*S_+s))*VD_ + col;
    float g = __half2float(G[goff]);
    o[goff] = __float2half((g / (1.0f + expf(-g))) * (yn * w[col] + bb[col]));
}

// ================= host launcher ============================================
extern "C" void kernel_launch(void* const* d_in, const int* in_sizes, int n_in,
                              void* d_out, int out_size)
{
    (void)in_sizes; (void)n_in; (void)out_size;
    const float* X      = (const float*)d_in[0];
    const float* Wq     = (const float*)d_in[1];
    const float* Wk     = (const float*)d_in[2];
    const float* Wv     = (const float*)d_in[3];
    const float* W_G    = (const float*)d_in[4];
    const float* W_O    = (const float*)d_in[5];
    const float* gn_w   = (const float*)d_in[6];
    const float* gn_b   = (const float*)d_in[7];
    const float* ln1_w  = (const float*)d_in[8];
    const float* ln1_b  = (const float*)d_in[9];
    const float* ln2_w  = (const float*)d_in[10];
    const float* ln2_b  = (const float*)d_in[11];
    const float* ffn_w1 = (const float*)d_in[12];
    const float* ffn_b1 = (const float*)d_in[13];
    const float* ffn_w2 = (const float*)d_in[14];
    const float* ffn_b2 = (const float*)d_in[15];
    float* out = (float*)d_out;

    float *Y,*X2,*xpt;
    f16 *Xn16,*Wqkv,*WGT,*WOT,*W1T,*W2T,*Q16,*K16,*Vt16,*Sc16,*G16,*h116;
    cudaGetSymbolAddress((void**)&Y,   d_Y);    cudaGetSymbolAddress((void**)&X2,  d_X2);
    cudaGetSymbolAddress((void**)&xpt, d_xpt);
    cudaGetSymbolAddress((void**)&Xn16,d_Xn16);
    cudaGetSymbolAddress((void**)&Wqkv,d_Wqkv);
    cudaGetSymbolAddress((void**)&WGT, d_WGT16);
    cudaGetSymbolAddress((void**)&WOT, d_WOT16);
    cudaGetSymbolAddress((void**)&W1T, d_W1T16);
    cudaGetSymbolAddress((void**)&W2T, d_W2T16);
    cudaGetSymbolAddress((void**)&Q16, d_Q16);  cudaGetSymbolAddress((void**)&K16, d_K16);
    cudaGetSymbolAddress((void**)&Vt16,d_Vt16);
    cudaGetSymbolAddress((void**)&Sc16,d_Sc16);
    cudaGetSymbolAddress((void**)&G16, d_G16);  cudaGetSymbolAddress((void**)&h116,d_h116);

    cudaFuncSetAttribute(tcgemm, cudaFuncAttributeMaxDynamicSharedMemorySize, SMEM_TC);

    // ---- single merged weight-prep launch ----
    long long qkvStride = 512LL * D_;
    WJobs J;
    // job 0: Wq -> Wqkv rows [0,128)   per head
    J.src[0]=Wq;     J.dst[0]=Wqkv; J.K[0]=D_;   J.N[0]=DK_;  J.oS[0]=qkvStride;          J.rOff[0]=0;
    // job 1: Wk -> Wqkv rows [128,256) per head
    J.src[1]=Wk;     J.dst[1]=Wqkv; J.K[1]=D_;   J.N[1]=DK_;  J.oS[1]=qkvStride;          J.rOff[1]=128;
    // job 2: Wv -> Wqkv rows [256,512) per head
    J.src[2]=Wv;     J.dst[2]=Wqkv; J.K[2]=D_;   J.N[2]=DV_;  J.oS[2]=qkvStride;          J.rOff[2]=256;
    // job 3: W_G
    J.src[3]=W_G;    J.dst[3]=WGT;  J.K[3]=D_;   J.N[3]=VD_;  J.oS[3]=(long long)VD_*D_;  J.rOff[3]=0;
    // job 4: W_O
    J.src[4]=W_O;    J.dst[4]=WOT;  J.K[4]=VD_;  J.N[4]=D_;   J.oS[4]=(long long)D_*VD_;  J.rOff[4]=0;
    // job 5: ffn_w1
    J.src[5]=ffn_w1; J.dst[5]=W1T;  J.K[5]=D_;   J.N[5]=FFN_; J.oS[5]=(long long)FFN_*D_; J.rOff[5]=0;
    // job 6: ffn_w2
    J.src[6]=ffn_w2; J.dst[6]=W2T;  J.K[6]=FFN_; J.N[6]=D_;   J.oS[6]=(long long)D_*FFN_; J.rOff[6]=0;
    int tot = 0;
    int zc[7] = {H_, H_, H_, 1, 1, 1, 1};
    for (int i = 0; i < 7; i++) {
        J.start[i] = tot;
        tot += (J.K[i] >> 5) * (J.N[i] >> 5) * zc[i];
    }
    J.start[7] = tot;
    wsplit_all<<<tot, dim3(32, 8)>>>(J);
    xpos_table_k<<<(S_*64+255)/256, 256>>>(xpt);

    // ln1
    layernorm_f16<<<NT_, 256>>>(X, ln1_w, ln1_b, Xn16);

    // merged QKV projection per head (fused xpos on Q/K, V written transposed)
    tcgemm<<<dim3(4,16,BH_), NTHREADS, SMEM_TC>>>(Xn16, Wqkv, Q16, K16, Vt16,
        nullptr, xpt, 512, D_,
        (long long)S_*D_, qkvStride, 0, H_, H_, 10);

    // G projection (fp16 out)
    tcgemm<<<dim3(16,32,1), NTHREADS, SMEM_TC>>>(Xn16, WGT, G16, nullptr, nullptr,
        nullptr, nullptr, VD_, D_, 0, 0, 0, 1, 1, 8);

    // scores = Q K^T (fused causal decay, fp16 out)
    tcgemm<<<dim3(16,16,BH_), NTHREADS, SMEM_TC>>>(Q16, K16, Sc16, nullptr, nullptr,
        nullptr, nullptr, S_, DK_,
        (long long)S_*DK_, (long long)S_*DK_, (long long)S_*S_, 1, BH_, 1);
    // Y = Sc V  (K-limited, fp32 out)
    tcgemm<<<dim3(2,16,BH_), NTHREADS, SMEM_TC>>>(Sc16, Vt16, Y, nullptr, nullptr,
        nullptr, nullptr, DV_, S_,
        (long long)S_*S_, (long long)DV_*S_, (long long)S_*DV_, 1, BH_, 2);

    // groupnorm + silu gate (in place)
    gnorm_gate_f16<<<B_*S_*H_, 256>>>(Y, G16, gn_w, gn_b, G16);

    // output projection + fused residual (X2 = G·W_O + X)
    tcgemm<<<dim3(8,32,1), NTHREADS, SMEM_TC>>>(G16, WOT, X2, nullptr, nullptr,
        nullptr, X, D_, VD_, 0, 0, 0, 1, 1, 4);

    // ln2 + FFN (bias+GELU fused; final bias+residual fused)
    layernorm_f16<<<NT_, 256>>>(X2, ln2_w, ln2_b, Xn16);
    tcgemm<<<dim3(32,32,1), NTHREADS, SMEM_TC>>>(Xn16, W1T, h116, nullptr, nullptr,
        ffn_b1, nullptr, FFN_, D_, 0, 0, 0, 1, 1, 3);
    tcgemm<<<dim3(8,32,1), NTHREADS, SMEM_TC>>>(h116, W2T, out, nullptr, nullptr,
        ffn_b2, X2, D_, FFN_, 0, 0, 0, 1, 1, 5);
}